// round 2
// baseline (speedup 1.0000x reference)
#include <cuda_runtime.h>

#define VOCABN 5000
#define NB 16
#define NS 128
#define NT 512
#define NL 257            // 2*NS + 1
#define NEGV (-1e30f)
#define ALPHA_W 0.2f
#define SMOOTH 0.1f
#define PF 7              // prefetch depth; 511 steps = 73 * 7

__device__ __forceinline__ float lae3(float a, float b, float c) {
    // logaddexp of three values; NEGV-safe (exp of huge negative -> 0)
    float m = fmaxf(a, fmaxf(b, c));
    float s = __expf(a - m) + __expf(b - m) + __expf(c - m);
    return m + __logf(s);
}

__global__ __launch_bounds__(288) void ctc_att_loss_kernel(
    const float* __restrict__ att,   // (16,128,5000)
    const float* __restrict__ ctc,   // (16,512,5000)  (treated as log-probs per reference)
    const int*   __restrict__ tgt,   // (16,128)
    float* __restrict__ out)
{
    __shared__ float Sa[2][NL + 1];
    __shared__ float red[9];

    const int tid = threadIdx.x;
    const int blk = blockIdx.x;

    if (blk < NB) {
        // ================= CTC forward for batch `blk` =================
        const float* cb = ctc + (size_t)blk * NT * VOCABN;
        const int*   tb = tgt + blk * NS;

        int   ext = 0;
        bool  allow2 = false;
        float a = NEGV;
        float eq[PF];

        if (tid < NL) {
            if (tid & 1) {
                ext = tb[tid >> 1];
                if (tid >= 3) {
                    int prev = tb[(tid - 3) >> 1];
                    allow2 = (ext != 0) && (ext != prev);
                }
            }
            // t = 0 init: alpha0[0]=emit[0][0], alpha0[1]=emit[0][1], else NEG
            float e0 = __ldg(cb + ext);
            a = (tid <= 1) ? e0 : NEGV;
            // preload emits for t = 1..PF
            #pragma unroll
            for (int i = 0; i < PF; ++i)
                eq[i] = __ldg(cb + (size_t)(1 + i) * VOCABN + ext);
        }

        int p = 0;
        for (int tt = 0; tt < (NT - 1) / PF; ++tt) {     // 73 outer iterations
            #pragma unroll
            for (int i = 0; i < PF; ++i) {               // slot i is compile-time
                const int t = 1 + tt * PF + i;
                if (tid < NL) Sa[p][tid] = a;            // publish alpha_{t-1}
                // issue prefetch for t+PF early (hides DRAM latency across PF steps)
                float en = 0.0f;
                const int tp = t + PF;
                if (tid < NL && tp < NT)
                    en = __ldg(cb + (size_t)tp * VOCABN + ext);
                __syncthreads();
                if (tid < NL) {
                    float e   = eq[i];
                    float am1 = (tid >= 1) ? Sa[p][tid - 1] : NEGV;
                    float am2 = allow2     ? Sa[p][tid - 2] : NEGV;
                    a = lae3(a, am1, am2) + e;
                    eq[i] = en;
                }
                p ^= 1;
            }
        }

        // final: ll = logaddexp(alpha[L-1], alpha[L-2])
        if (tid < NL) Sa[0][tid] = a;
        __syncthreads();
        if (tid == 0) {
            float ll = lae3(Sa[0][NL - 1], Sa[0][NL - 2], NEGV);
            float lb = -ll;
            if (lb > 1e20f) lb = 0.0f;               // zero_infinity
            // (1-ALPHA) * mean_b( loss_b / S )
            atomicAdd(out, ((1.0f - ALPHA_W) / (float)(NB * NS)) * lb);
        }
    } else {
        // ================= label-smoothing row `blk - NB` =================
        const int r = blk - NB;                       // 0..2047
        const float* row = att + (size_t)r * VOCABN;
        const int tv = tgt[r];

        float s = 0.0f;
        const float4* row4 = (const float4*)row;      // 5000 % 4 == 0
        for (int i = tid; i < VOCABN / 4; i += 288) {
            float4 v = row4[i];
            s += (v.x + v.y) + (v.z + v.w);
        }
        #pragma unroll
        for (int o = 16; o > 0; o >>= 1)
            s += __shfl_down_sync(0xffffffffu, s, o);
        const int wid = tid >> 5, lane = tid & 31;
        if (lane == 0) red[wid] = s;
        __syncthreads();
        if (tid == 0) {
            float total = 0.0f;
            #pragma unroll
            for (int w = 0; w < 9; ++w) total += red[w];
            float tl = __ldg(row + tv);
            const float conf = 1.0f - SMOOTH;
            const float off  = SMOOTH / (float)(VOCABN - 1);
            float per_row = -(off * total + (conf - off) * tl);
            // ALPHA * mean over 2048 rows
            atomicAdd(out, (ALPHA_W / 2048.0f) * per_row);
        }
    }
}

extern "C" void kernel_launch(void* const* d_in, const int* in_sizes, int n_in,
                              void* d_out, int out_size) {
    const float* att = (const float*)d_in[0];
    const float* ctc = (const float*)d_in[1];
    const int*   tgt = (const int*)d_in[2];
    float* out = (float*)d_out;

    cudaMemsetAsync(out, 0, sizeof(float));
    ctc_att_loss_kernel<<<NB + NB * NS, 288>>>(att, ctc, tgt, out);
}

// round 5
// speedup vs baseline: 2.4753x; 2.4753x over previous
#include <cuda_runtime.h>
#include <cuda_pipeline.h>

#define VOCABN 5000
#define NB 16
#define NS 128
#define NT 512
#define NL 257            // 2*NS + 1
#define NEGV (-1e30f)
#define ALPHA_W 0.2f
#define SMOOTH 0.1f
#define DPTH 8            // cp.async pipeline depth (power of two)
#define RSTR 260          // ring slot stride in floats

__device__ __forceinline__ float lae3(float a, float b, float c) {
    // logaddexp of three values; NEGV-safe (exp of huge negative -> 0)
    float m = fmaxf(a, fmaxf(b, c));
    float s = __expf(a - m) + __expf(b - m) + __expf(c - m);
    return m + __logf(s);
}

__global__ __launch_bounds__(288) void ctc_att_loss_kernel(
    const float* __restrict__ att,   // (16,128,5000)
    const float* __restrict__ ctc,   // (16,512,5000) treated as log-probs (matches reference)
    const int*   __restrict__ tgt,   // (16,128)
    float* __restrict__ out)
{
    __shared__ float Sa[2][NL + 1];
    __shared__ float ring[DPTH * RSTR];
    __shared__ float red[9];

    const int tid = threadIdx.x;
    const int blk = blockIdx.x;

    if (blk < NB) {
        // ================= CTC forward for batch `blk` =================
        const float* cb = ctc + (size_t)blk * NT * VOCABN;
        const int*   tb = tgt + blk * NS;

        int   ext = 0;
        bool  allow2 = false;
        float a = NEGV;
        const float* col = cb;       // this thread's emit column pointer

        if (tid < NL) {
            if (tid & 1) {
                ext = tb[tid >> 1];
                if (tid >= 3) {
                    int prev = tb[(tid - 3) >> 1];
                    allow2 = (ext != 0) && (ext != prev);
                }
            }
            col = cb + ext;
            // t = 0 init: alpha0[0]=emit[0][0], alpha0[1]=emit[0][1], else NEG
            a = (tid <= 1) ? __ldg(col) : NEGV;
            // prologue: stage emits for t = 1..DPTH, one commit group per step
            #pragma unroll
            for (int d = 0; d < DPTH; ++d) {
                __pipeline_memcpy_async(&ring[d * RSTR + tid],
                                        col + (size_t)(1 + d) * VOCABN, 4);
                __pipeline_commit();
            }
        }

        int p = 0;
        for (int t = 1; t < NT; ++t) {
            const int s = (t - 1) & (DPTH - 1);
            if (tid < NL) {
                Sa[p][tid] = a;                      // publish alpha_{t-1}
                __pipeline_wait_prior(DPTH - 1);     // emit for step t has landed
            }
            __syncthreads();
            if (tid < NL) {
                float e = ring[s * RSTR + tid];
                // refill this slot for step t+DPTH (own-thread address; no race)
                const int tp = t + DPTH;
                if (tp < NT)
                    __pipeline_memcpy_async(&ring[s * RSTR + tid],
                                            col + (size_t)tp * VOCABN, 4);
                __pipeline_commit();                 // exactly one group per step
                float am1 = (tid >= 1) ? Sa[p][tid - 1] : NEGV;
                float am2 = allow2     ? Sa[p][tid - 2] : NEGV;
                a = lae3(a, am1, am2) + e;
            }
            p ^= 1;
        }

        // final: ll = logaddexp(alpha[L-1], alpha[L-2])
        if (tid < NL) Sa[0][tid] = a;
        __syncthreads();
        if (tid == 0) {
            float ll = lae3(Sa[0][NL - 1], Sa[0][NL - 2], NEGV);
            float lb = -ll;
            if (lb > 1e20f) lb = 0.0f;               // zero_infinity
            atomicAdd(out, ((1.0f - ALPHA_W) / (float)(NB * NS)) * lb);
        }
    } else {
        // ================= label-smoothing row `blk - NB` =================
        const int r = blk - NB;                       // 0..2047
        const float* row = att + (size_t)r * VOCABN;
        const int tv = tgt[r];

        float s = 0.0f;
        const float4* row4 = (const float4*)row;      // 5000 % 4 == 0
        for (int i = tid; i < VOCABN / 4; i += 288) {
            float4 v = row4[i];
            s += (v.x + v.y) + (v.z + v.w);
        }
        #pragma unroll
        for (int o = 16; o > 0; o >>= 1)
            s += __shfl_down_sync(0xffffffffu, s, o);
        const int wid = tid >> 5, lane = tid & 31;
        if (lane == 0) red[wid] = s;
        __syncthreads();
        if (tid == 0) {
            float total = 0.0f;
            #pragma unroll
            for (int w = 0; w < 9; ++w) total += red[w];
            float tl = __ldg(row + tv);
            const float conf = 1.0f - SMOOTH;
            const float off  = SMOOTH / (float)(VOCABN - 1);
            float per_row = -(off * total + (conf - off) * tl);
            atomicAdd(out, (ALPHA_W / 2048.0f) * per_row);
        }
    }
}

extern "C" void kernel_launch(void* const* d_in, const int* in_sizes, int n_in,
                              void* d_out, int out_size) {
    const float* att = (const float*)d_in[0];
    const float* ctc = (const float*)d_in[1];
    const int*   tgt = (const int*)d_in[2];
    float* out = (float*)d_out;

    cudaMemsetAsync(out, 0, sizeof(float));
    ctc_att_loss_kernel<<<NB + NB * NS, 288>>>(att, ctc, tgt, out);
}